// round 4
// baseline (speedup 1.0000x reference)
#include <cuda_runtime.h>
#include <math.h>

#define NN 100000
#define EE 600000
#define DIN 256
#define DH  128
#define DE  64

// ---------------- scratch (static device globals; no allocation) ------------
__device__ float g_h   [(size_t)NN * DH];  // GEMM output (pre-aggregation)
__device__ float g_agg [(size_t)NN * DH];  // scatter accumulator
__device__ float g_h1  [(size_t)NN * DH];  // layer activation buffer
__device__ float g_din [NN];               // deg -> dinv
__device__ int   g_src [EE];
__device__ int   g_dst [EE];
__device__ float g_coef[EE];               // dinv[src]*dinv[dst]
__device__ int   g_is64;

__device__ __forceinline__ float* bufptr(int id) {
    switch (id) {
        case 0:  return g_h;
        case 1:  return g_agg;
        case 2:  return g_h1;
        default: return g_din;
    }
}

// ---------------- edge-index dtype detection + conversion -------------------
// int64 little-endian with values in [0, 2^31): odd 32-bit words are all 0.
__global__ void detect_kernel(const int* __restrict__ w) {
    if (threadIdx.x == 0 && blockIdx.x == 0) {
        int is64 = 1;
        for (int i = 1; i < 128; i += 2)
            if (w[i] != 0) { is64 = 0; break; }
        g_is64 = is64;
    }
}

__global__ void convert_kernel(const void* __restrict__ ei) {
    int e = blockIdx.x * blockDim.x + threadIdx.x;
    if (e >= 2 * EE) return;
    int v;
    if (g_is64) v = (int)((const long long*)ei)[e];
    else        v = ((const int*)ei)[e];
    v = max(0, min(NN - 1, v));   // clamp: wrong dtype -> bad rel_err, not a crash
    if (e < EE) g_src[e] = v;
    else        g_dst[e - EE] = v;
}

// ---------------- graph-structure kernels ------------------------------------
__global__ void zero_din() {
    int i = blockIdx.x * blockDim.x + threadIdx.x;
    if (i < NN) g_din[i] = 0.0f;
}

__global__ void deg_kernel() {
    int e = blockIdx.x * blockDim.x + threadIdx.x;
    if (e < EE) atomicAdd(&g_din[g_dst[e]], 1.0f);
}

__global__ void dinv_kernel() {
    int i = blockIdx.x * blockDim.x + threadIdx.x;
    if (i < NN) g_din[i] = rsqrtf(g_din[i] + 1.0f);
}

__global__ void coef_kernel() {
    int e = blockIdx.x * blockDim.x + threadIdx.x;
    if (e < EE) g_coef[e] = g_din[g_src[e]] * g_din[g_dst[e]];
}

// ---------------- elementwise -------------------------------------------------
__global__ void fill_zero(int id, size_t n) {
    size_t i = (size_t)blockIdx.x * blockDim.x + threadIdx.x;
    float* p = bufptr(id);
    if (i < n) p[i] = 0.0f;
}

// gather g_h[src]*coef, atomic scatter-add into g_agg[dst]; 4 feats/thread
__global__ void scatter_kernel(int D) {
    long long t = (long long)blockIdx.x * blockDim.x + threadIdx.x;
    int per = D >> 2;
    long long total = (long long)EE * per;
    if (t >= total) return;
    int e = (int)(t / per);
    int f = (int)(t - (long long)e * per) * 4;
    int s = g_src[e];
    int d = g_dst[e];
    float coef = g_coef[e];
    const float4 v = *reinterpret_cast<const float4*>(g_h + (size_t)s * D + f);
    float* a = g_agg + (size_t)d * D + f;
    atomicAdd(a + 0, v.x * coef);
    atomicAdd(a + 1, v.y * coef);
    atomicAdd(a + 2, v.z * coef);
    atomicAdd(a + 3, v.w * coef);
}

// out = g_agg + g_h * dinv^2 + bias, optional relu
__global__ void finalize_kernel(const float* __restrict__ b,
                                float* out_ext, int out_id,
                                int D, int do_relu) {
    size_t idx = (size_t)blockIdx.x * blockDim.x + threadIdx.x;
    size_t total = (size_t)NN * D;
    if (idx >= total) return;
    float* out = out_ext ? out_ext : bufptr(out_id);
    int i = (int)(idx / D);
    int f = (int)(idx - (size_t)i * D);
    float di = g_din[i];
    float v = g_agg[idx] + g_h[idx] * di * di + b[f];
    if (do_relu) v = fmaxf(v, 0.0f);
    out[idx] = v;
}

// ---------------- SGEMM: C[N,M] = A[N,K] @ B[K,M] (+bias)(+relu) -------------
#define BM 64
#define BN 64
#define BK 16

__global__ void gemm_kernel(const float* A_ext, int a_id,
                            const float* __restrict__ B,
                            const float* __restrict__ bias,
                            float* C_ext, int c_id,
                            int N, int K, int M, int do_relu) {
    __shared__ float As[BK][BM];
    __shared__ float Bs[BK][BN];

    const float* A = A_ext ? A_ext : bufptr(a_id);
    float*       C = C_ext ? C_ext : bufptr(c_id);

    int row0 = blockIdx.y * BM;
    int col0 = blockIdx.x * BN;
    int tid  = threadIdx.x;
    int tx = tid & 15;
    int ty = tid >> 4;

    float acc[4][4];
#pragma unroll
    for (int i = 0; i < 4; i++)
#pragma unroll
        for (int j = 0; j < 4; j++) acc[i][j] = 0.0f;

    for (int k0 = 0; k0 < K; k0 += BK) {
#pragma unroll
        for (int i = tid; i < BM * BK; i += 256) {
            int r = i >> 4;
            int c = i & 15;
            int gr = row0 + r;
            As[c][r] = (gr < N) ? A[(size_t)gr * K + k0 + c] : 0.0f;
        }
#pragma unroll
        for (int i = tid; i < BK * BN; i += 256) {
            int r = i >> 6;
            int c = i & 63;
            Bs[r][c] = B[(size_t)(k0 + r) * M + col0 + c];
        }
        __syncthreads();
#pragma unroll
        for (int k = 0; k < BK; k++) {
            float a[4], bb[4];
#pragma unroll
            for (int i = 0; i < 4; i++) a[i]  = As[k][ty * 4 + i];
#pragma unroll
            for (int j = 0; j < 4; j++) bb[j] = Bs[k][tx * 4 + j];
#pragma unroll
            for (int i = 0; i < 4; i++)
#pragma unroll
                for (int j = 0; j < 4; j++) acc[i][j] += a[i] * bb[j];
        }
        __syncthreads();
    }

#pragma unroll
    for (int i = 0; i < 4; i++) {
        int r = row0 + ty * 4 + i;
        if (r >= N) continue;
#pragma unroll
        for (int j = 0; j < 4; j++) {
            int c = col0 + tx * 4 + j;
            float v = acc[i][j];
            if (bias) v += bias[c];
            if (do_relu) v = fmaxf(v, 0.0f);
            C[(size_t)r * M + c] = v;
        }
    }
}

// ---------------- orchestration ----------------------------------------------
// ids: 0 = g_h, 1 = g_agg, 2 = g_h1, 3 = g_din

static inline void run_gemm(const float* A_ext, int a_id, const float* B,
                            const float* bias, float* C_ext, int c_id,
                            int n, int K, int M, int relu) {
    dim3 grid(M / BN, (n + BM - 1) / BM);
    gemm_kernel<<<grid, 256>>>(A_ext, a_id, B, bias, C_ext, c_id, n, K, M, relu);
}

static inline void run_fill(int id, size_t n) {
    fill_zero<<<(int)((n + 255) / 256), 256>>>(id, n);
}

static inline void run_scatter(int D) {
    long long total = (long long)EE * (D >> 2);
    scatter_kernel<<<(int)((total + 255) / 256), 256>>>(D);
}

static inline void run_finalize(const float* b, float* out_ext, int out_id,
                                int D, int relu) {
    size_t total = (size_t)NN * D;
    finalize_kernel<<<(int)((total + 255) / 256), 256>>>(b, out_ext, out_id, D, relu);
}

extern "C" void kernel_launch(void* const* d_in, const int* in_sizes, int n_in,
                              void* d_out, int out_size) {
    const float* x   = (const float*)d_in[0];
    const void*  ei  = d_in[1];
    const float* W1  = (const float*)d_in[2];
    const float* b1  = (const float*)d_in[3];
    const float* W2  = (const float*)d_in[4];
    const float* b2  = (const float*)d_in[5];
    const float* W3  = (const float*)d_in[6];
    const float* b3  = (const float*)d_in[7];
    const float* Wd1 = (const float*)d_in[8];
    const float* bd1 = (const float*)d_in[9];
    const float* Wd2 = (const float*)d_in[10];
    const float* bd2 = (const float*)d_in[11];

    float* z    = (float*)d_out;                     // [N, 64]
    float* xhat = (float*)d_out + (size_t)NN * DE;   // [N, 256]

    // edge index: detect dtype, convert to int32, build degrees + coefs
    detect_kernel<<<1, 32>>>((const int*)ei);
    convert_kernel<<<(2 * EE + 255) / 256, 256>>>(ei);
    zero_din<<<(NN + 255) / 256, 256>>>();
    deg_kernel<<<(EE + 255) / 256, 256>>>();
    dinv_kernel<<<(NN + 255) / 256, 256>>>();
    coef_kernel<<<(EE + 255) / 256, 256>>>();

    // ---- layer 1: h1 = relu(gcn(x, W1, b1)) -----------------------------
    run_gemm(x, -1, W1, nullptr, nullptr, 0, NN, DIN, DH, 0);   // g_h = x@W1
    run_fill(1, (size_t)NN * DH);
    run_scatter(DH);
    run_finalize(b1, nullptr, 2, DH, 1);                        // -> g_h1

    // ---- layer 2: h2 = relu(gcn(h1, W2, b2)) ----------------------------
    run_gemm(nullptr, 2, W2, nullptr, nullptr, 0, NN, DH, DH, 0);
    run_fill(1, (size_t)NN * DH);
    run_scatter(DH);
    run_finalize(b2, nullptr, 2, DH, 1);

    // ---- layer 3: z = gcn(h2, W3, b3) -----------------------------------
    run_gemm(nullptr, 2, W3, nullptr, nullptr, 0, NN, DH, DE, 0);
    run_fill(1, (size_t)NN * DE);
    run_scatter(DE);
    run_finalize(b3, z, -1, DE, 0);

    // ---- decoder: x_hat = relu(z@Wd1+bd1)@Wd2 + bd2 ---------------------
    run_gemm(z, -1, Wd1, bd1, nullptr, 2, NN, DE, DH, 1);
    run_gemm(nullptr, 2, Wd2, bd2, xhat, -1, NN, DH, DIN, 0);
}

// round 5
// speedup vs baseline: 1.5703x; 1.5703x over previous
#include <cuda_runtime.h>
#include <math.h>

#define NN 100000
#define EE 600000
#define DIN 256
#define DH  128
#define DE  64
#define NB  ((NN + 1023) / 1024)

// ---------------- scratch (static device globals; no allocation) ------------
__device__ float g_h   [(size_t)NN * DH];  // GEMM output (pre-aggregation)
__device__ float g_h1  [(size_t)NN * DH];  // layer activation buffer
__device__ float g_din [NN];               // 1/sqrt(deg+1)
__device__ int   g_cnt [NN];               // in-degree counts
__device__ int   g_rowptr[NN + 1];         // CSR row pointers (by dst)
__device__ int   g_cur [NN];               // placement cursors
__device__ int   g_bsum[NB];               // scan block sums
__device__ int   g_ssrc [EE];              // CSR: src node per sorted edge
__device__ float g_scoef[EE];              // CSR: dinv[src]*dinv[dst]
__device__ int   g_src[EE];
__device__ int   g_dst[EE];
__device__ int   g_is64;

__device__ __forceinline__ float* bufptr(int id) {
    switch (id) {
        case 0:  return g_h;
        default: return g_h1;
    }
}

// ---------------- edge-index dtype detection + conversion -------------------
__global__ void detect_kernel(const int* __restrict__ w) {
    if (threadIdx.x == 0 && blockIdx.x == 0) {
        int is64 = 1;
        for (int i = 1; i < 128; i += 2)
            if (w[i] != 0) { is64 = 0; break; }
        g_is64 = is64;
    }
}

__global__ void convert_kernel(const void* __restrict__ ei) {
    int e = blockIdx.x * blockDim.x + threadIdx.x;
    if (e >= 2 * EE) return;
    int v;
    if (g_is64) v = (int)((const long long*)ei)[e];
    else        v = ((const int*)ei)[e];
    v = max(0, min(NN - 1, v));
    if (e < EE) g_src[e] = v;
    else        g_dst[e - EE] = v;
}

// ---------------- CSR construction -------------------------------------------
__global__ void zero_cnt_kernel() {
    int i = blockIdx.x * blockDim.x + threadIdx.x;
    if (i < NN) g_cnt[i] = 0;
}

__global__ void count_kernel() {
    int e = blockIdx.x * blockDim.x + threadIdx.x;
    if (e < EE) atomicAdd(&g_cnt[g_dst[e]], 1);
}

__global__ void dinv_kernel() {
    int i = blockIdx.x * blockDim.x + threadIdx.x;
    if (i < NN) g_din[i] = rsqrtf((float)g_cnt[i] + 1.0f);
}

// block-level inclusive scan of counts -> rowptr[i+1], block sums
__global__ void scan1_kernel() {
    __shared__ int s[1024];
    int i = blockIdx.x * 1024 + threadIdx.x;
    int v = (i < NN) ? g_cnt[i] : 0;
    s[threadIdx.x] = v;
    __syncthreads();
    for (int off = 1; off < 1024; off <<= 1) {
        int t = (threadIdx.x >= off) ? s[threadIdx.x - off] : 0;
        __syncthreads();
        s[threadIdx.x] += t;
        __syncthreads();
    }
    if (i < NN) g_rowptr[i + 1] = s[threadIdx.x];
    if (threadIdx.x == 1023) g_bsum[blockIdx.x] = s[1023];
}

__global__ void scan2_kernel() {
    if (threadIdx.x == 0 && blockIdx.x == 0) {
        int run = 0;
        for (int b = 0; b < NB; b++) { int t = g_bsum[b]; g_bsum[b] = run; run += t; }
        g_rowptr[0] = 0;
    }
}

__global__ void scan3_kernel() {
    int i = blockIdx.x * blockDim.x + threadIdx.x;
    if (i < NN) g_rowptr[i + 1] += g_bsum[i >> 10];
}

__global__ void curinit_kernel() {
    int i = blockIdx.x * blockDim.x + threadIdx.x;
    if (i < NN) g_cur[i] = g_rowptr[i];
}

__global__ void fill_csr_kernel() {
    int e = blockIdx.x * blockDim.x + threadIdx.x;
    if (e >= EE) return;
    int s = g_src[e];
    int d = g_dst[e];
    int slot = atomicAdd(&g_cur[d], 1);
    g_ssrc[slot]  = s;
    g_scoef[slot] = g_din[s] * g_din[d];
}

// ---------------- fused aggregation (gather + self-loop + bias + relu) -------
// one warp per dst node; D=128 -> float4/lane
__global__ void agg_d128_kernel(const float* __restrict__ bias,
                                float* out_ext, int out_id, int do_relu) {
    int warp = (blockIdx.x * blockDim.x + threadIdx.x) >> 5;
    int lane = threadIdx.x & 31;
    if (warp >= NN) return;
    float* out = out_ext ? out_ext : bufptr(out_id);
    int rs = g_rowptr[warp], re = g_rowptr[warp + 1];
    float di = g_din[warp];
    float sc = di * di;
    float4 acc = *reinterpret_cast<const float4*>(g_h + (size_t)warp * 128 + lane * 4);
    acc.x *= sc; acc.y *= sc; acc.z *= sc; acc.w *= sc;
    for (int j = rs; j < re; j++) {
        int s = g_ssrc[j];
        float c = g_scoef[j];
        float4 v = *reinterpret_cast<const float4*>(g_h + (size_t)s * 128 + lane * 4);
        acc.x += v.x * c; acc.y += v.y * c; acc.z += v.z * c; acc.w += v.w * c;
    }
    float4 b = *reinterpret_cast<const float4*>(bias + lane * 4);
    acc.x += b.x; acc.y += b.y; acc.z += b.z; acc.w += b.w;
    if (do_relu) {
        acc.x = fmaxf(acc.x, 0.0f); acc.y = fmaxf(acc.y, 0.0f);
        acc.z = fmaxf(acc.z, 0.0f); acc.w = fmaxf(acc.w, 0.0f);
    }
    *reinterpret_cast<float4*>(out + (size_t)warp * 128 + lane * 4) = acc;
}

// D=64 -> float2/lane
__global__ void agg_d64_kernel(const float* __restrict__ bias,
                               float* out_ext, int out_id, int do_relu) {
    int warp = (blockIdx.x * blockDim.x + threadIdx.x) >> 5;
    int lane = threadIdx.x & 31;
    if (warp >= NN) return;
    float* out = out_ext ? out_ext : bufptr(out_id);
    int rs = g_rowptr[warp], re = g_rowptr[warp + 1];
    float di = g_din[warp];
    float sc = di * di;
    float2 acc = *reinterpret_cast<const float2*>(g_h + (size_t)warp * 64 + lane * 2);
    acc.x *= sc; acc.y *= sc;
    for (int j = rs; j < re; j++) {
        int s = g_ssrc[j];
        float c = g_scoef[j];
        float2 v = *reinterpret_cast<const float2*>(g_h + (size_t)s * 64 + lane * 2);
        acc.x += v.x * c; acc.y += v.y * c;
    }
    float2 b = *reinterpret_cast<const float2*>(bias + lane * 2);
    acc.x += b.x; acc.y += b.y;
    if (do_relu) { acc.x = fmaxf(acc.x, 0.0f); acc.y = fmaxf(acc.y, 0.0f); }
    *reinterpret_cast<float2*>(out + (size_t)warp * 64 + lane * 2) = acc;
}

// ---------------- SGEMM: C[N,M] = A[N,K] @ B[K,M] (+bias)(+relu) -------------
#define BM 64
#define BN 64
#define BK 16

__global__ void gemm_kernel(const float* A_ext, int a_id,
                            const float* __restrict__ B,
                            const float* __restrict__ bias,
                            float* C_ext, int c_id,
                            int N, int K, int M, int do_relu) {
    __shared__ float As[BK][BM + 4];   // pad: 2-way instead of 16-way STS conflicts
    __shared__ float Bs[BK][BN];

    const float* A = A_ext ? A_ext : bufptr(a_id);
    float*       C = C_ext ? C_ext : bufptr(c_id);

    int row0 = blockIdx.y * BM;
    int col0 = blockIdx.x * BN;
    int tid  = threadIdx.x;
    int tx = tid & 15;
    int ty = tid >> 4;

    float acc[4][4];
#pragma unroll
    for (int i = 0; i < 4; i++)
#pragma unroll
        for (int j = 0; j < 4; j++) acc[i][j] = 0.0f;

    for (int k0 = 0; k0 < K; k0 += BK) {
        // A tile (transposed store): each thread 4 elements
#pragma unroll
        for (int i = tid; i < BM * BK; i += 256) {
            int r = i >> 4;          // row within tile
            int c = i & 15;          // k within tile
            int gr = row0 + r;
            As[c][r] = (gr < N) ? A[(size_t)gr * K + k0 + c] : 0.0f;
        }
        // B tile
#pragma unroll
        for (int i = tid; i < BK * BN; i += 256) {
            int r = i >> 6;
            int c = i & 63;
            Bs[r][c] = B[(size_t)(k0 + r) * M + col0 + c];
        }
        __syncthreads();
#pragma unroll
        for (int k = 0; k < BK; k++) {
            float4 a = *reinterpret_cast<const float4*>(&As[k][ty * 4]);
            float4 b = *reinterpret_cast<const float4*>(&Bs[k][tx * 4]);
            acc[0][0] += a.x * b.x; acc[0][1] += a.x * b.y; acc[0][2] += a.x * b.z; acc[0][3] += a.x * b.w;
            acc[1][0] += a.y * b.x; acc[1][1] += a.y * b.y; acc[1][2] += a.y * b.z; acc[1][3] += a.y * b.w;
            acc[2][0] += a.z * b.x; acc[2][1] += a.z * b.y; acc[2][2] += a.z * b.z; acc[2][3] += a.z * b.w;
            acc[3][0] += a.w * b.x; acc[3][1] += a.w * b.y; acc[3][2] += a.w * b.z; acc[3][3] += a.w * b.w;
        }
        __syncthreads();
    }

#pragma unroll
    for (int i = 0; i < 4; i++) {
        int r = row0 + ty * 4 + i;
        if (r >= N) continue;
#pragma unroll
        for (int j = 0; j < 4; j++) {
            int c = col0 + tx * 4 + j;
            float v = acc[i][j];
            if (bias) v += bias[c];
            if (do_relu) v = fmaxf(v, 0.0f);
            C[(size_t)r * M + c] = v;
        }
    }
}

// ---------------- orchestration ----------------------------------------------
// buffer ids: 0 = g_h, 2 = g_h1

static inline void run_gemm(const float* A_ext, int a_id, const float* B,
                            const float* bias, float* C_ext, int c_id,
                            int n, int K, int M, int relu) {
    dim3 grid(M / BN, (n + BM - 1) / BM);
    gemm_kernel<<<grid, 256>>>(A_ext, a_id, B, bias, C_ext, c_id, n, K, M, relu);
}

static inline void run_agg128(const float* b, float* out_ext, int out_id, int relu) {
    int warps_per_block = 8;                       // 256 threads
    int blocks = (NN + warps_per_block - 1) / warps_per_block;
    agg_d128_kernel<<<blocks, 256>>>(b, out_ext, out_id, relu);
}

static inline void run_agg64(const float* b, float* out_ext, int out_id, int relu) {
    int warps_per_block = 8;
    int blocks = (NN + warps_per_block - 1) / warps_per_block;
    agg_d64_kernel<<<blocks, 256>>>(b, out_ext, out_id, relu);
}

extern "C" void kernel_launch(void* const* d_in, const int* in_sizes, int n_in,
                              void* d_out, int out_size) {
    const float* x   = (const float*)d_in[0];
    const void*  ei  = d_in[1];
    const float* W1  = (const float*)d_in[2];
    const float* b1  = (const float*)d_in[3];
    const float* W2  = (const float*)d_in[4];
    const float* b2  = (const float*)d_in[5];
    const float* W3  = (const float*)d_in[6];
    const float* b3  = (const float*)d_in[7];
    const float* Wd1 = (const float*)d_in[8];
    const float* bd1 = (const float*)d_in[9];
    const float* Wd2 = (const float*)d_in[10];
    const float* bd2 = (const float*)d_in[11];

    float* z    = (float*)d_out;                     // [N, 64]
    float* xhat = (float*)d_out + (size_t)NN * DE;   // [N, 256]

    // ---- graph preprocessing: dtype convert + CSR build -----------------
    detect_kernel<<<1, 32>>>((const int*)ei);
    convert_kernel<<<(2 * EE + 255) / 256, 256>>>(ei);
    zero_cnt_kernel<<<(NN + 255) / 256, 256>>>();
    count_kernel<<<(EE + 255) / 256, 256>>>();
    dinv_kernel<<<(NN + 255) / 256, 256>>>();
    scan1_kernel<<<NB, 1024>>>();
    scan2_kernel<<<1, 32>>>();
    scan3_kernel<<<(NN + 255) / 256, 256>>>();
    curinit_kernel<<<(NN + 255) / 256, 256>>>();
    fill_csr_kernel<<<(EE + 255) / 256, 256>>>();

    // ---- layer 1: h1 = relu(gcn(x, W1, b1)) -----------------------------
    run_gemm(x, -1, W1, nullptr, nullptr, 0, NN, DIN, DH, 0);   // g_h = x@W1
    run_agg128(b1, nullptr, 2, 1);                              // -> g_h1

    // ---- layer 2: h2 = relu(gcn(h1, W2, b2)) ----------------------------
    run_gemm(nullptr, 2, W2, nullptr, nullptr, 0, NN, DH, DH, 0);
    run_agg128(b2, nullptr, 2, 1);

    // ---- layer 3: z = gcn(h2, W3, b3) -----------------------------------
    run_gemm(nullptr, 2, W3, nullptr, nullptr, 0, NN, DH, DE, 0);
    run_agg64(b3, z, -1, 0);

    // ---- decoder: x_hat = relu(z@Wd1+bd1)@Wd2 + bd2 ---------------------
    run_gemm(z, -1, Wd1, bd1, nullptr, 2, NN, DE, DH, 1);
    run_gemm(nullptr, 2, Wd2, bd2, xhat, -1, NN, DH, DIN, 0);
}

// round 6
// speedup vs baseline: 2.5297x; 1.6109x over previous
#include <cuda_runtime.h>
#include <math.h>
#include <stdint.h>

#define NN 100000
#define EE 600000
#define DIN 256
#define DH  128
#define DE  64
#define NB  ((NN + 1023) / 1024)

// ---------------- scratch (static device globals; no allocation) ------------
__device__ float g_h   [(size_t)NN * DH];  // GEMM output (pre-aggregation)
__device__ float g_h1  [(size_t)NN * DH];  // layer activation buffer
__device__ float g_din [NN];               // 1/sqrt(deg+1)
__device__ int   g_cnt [NN];               // in-degree counts
__device__ int   g_rowptr[NN + 1];         // CSR row pointers (by dst)
__device__ int   g_cur [NN];               // placement cursors
__device__ int   g_bsum[NB];               // scan block sums
__device__ int   g_ssrc [EE];              // CSR: src node per sorted edge
__device__ float g_scoef[EE];              // CSR: dinv[src]*dinv[dst]
__device__ int   g_src[EE];
__device__ int   g_dst[EE];
__device__ int   g_is64;

__device__ __forceinline__ float* bufptr(int id) {
    switch (id) {
        case 0:  return g_h;
        default: return g_h1;
    }
}

// ---------------- edge-index dtype detection + conversion -------------------
__global__ void detect_kernel(const int* __restrict__ w) {
    if (threadIdx.x == 0 && blockIdx.x == 0) {
        int is64 = 1;
        for (int i = 1; i < 128; i += 2)
            if (w[i] != 0) { is64 = 0; break; }
        g_is64 = is64;
    }
}

// convert + clamp + count in-degree (dst side) in one pass
__global__ void convert_kernel(const void* __restrict__ ei) {
    int e = blockIdx.x * blockDim.x + threadIdx.x;
    if (e >= 2 * EE) return;
    int v;
    if (g_is64) v = (int)((const long long*)ei)[e];
    else        v = ((const int*)ei)[e];
    v = max(0, min(NN - 1, v));
    if (e < EE) g_src[e] = v;
    else        { g_dst[e - EE] = v; atomicAdd(&g_cnt[v], 1); }
}

// ---------------- CSR construction -------------------------------------------
__global__ void zero_cnt_kernel() {
    int i = blockIdx.x * blockDim.x + threadIdx.x;
    if (i < NN) g_cnt[i] = 0;
}

__global__ void dinv_kernel() {
    int i = blockIdx.x * blockDim.x + threadIdx.x;
    if (i < NN) g_din[i] = rsqrtf((float)g_cnt[i] + 1.0f);
}

__global__ void scan1_kernel() {
    __shared__ int s[1024];
    int i = blockIdx.x * 1024 + threadIdx.x;
    int v = (i < NN) ? g_cnt[i] : 0;
    s[threadIdx.x] = v;
    __syncthreads();
    for (int off = 1; off < 1024; off <<= 1) {
        int t = (threadIdx.x >= off) ? s[threadIdx.x - off] : 0;
        __syncthreads();
        s[threadIdx.x] += t;
        __syncthreads();
    }
    if (i < NN) g_rowptr[i + 1] = s[threadIdx.x];
    if (threadIdx.x == 1023) g_bsum[blockIdx.x] = s[1023];
}

__global__ void scan2_kernel() {
    if (threadIdx.x == 0 && blockIdx.x == 0) {
        int run = 0;
        for (int b = 0; b < NB; b++) { int t = g_bsum[b]; g_bsum[b] = run; run += t; }
        g_rowptr[0] = 0;
    }
}

__global__ void scan3_kernel() {
    int i = blockIdx.x * blockDim.x + threadIdx.x;
    if (i < NN) g_rowptr[i + 1] += g_bsum[i >> 10];
}

__global__ void curinit_kernel() {
    int i = blockIdx.x * blockDim.x + threadIdx.x;
    if (i < NN) g_cur[i] = g_rowptr[i];
}

__global__ void fill_csr_kernel() {
    int e = blockIdx.x * blockDim.x + threadIdx.x;
    if (e >= EE) return;
    int s = g_src[e];
    int d = g_dst[e];
    int slot = atomicAdd(&g_cur[d], 1);
    g_ssrc[slot]  = s;
    g_scoef[slot] = g_din[s] * g_din[d];
}

// ---------------- fused aggregation (gather + self-loop + bias + relu) -------
__global__ void agg_d128_kernel(const float* __restrict__ bias,
                                float* out_ext, int out_id, int do_relu) {
    int warp = (blockIdx.x * blockDim.x + threadIdx.x) >> 5;
    int lane = threadIdx.x & 31;
    if (warp >= NN) return;
    float* out = out_ext ? out_ext : bufptr(out_id);
    int rs = g_rowptr[warp], re = g_rowptr[warp + 1];
    float di = g_din[warp];
    float sc = di * di;
    float4 acc = *reinterpret_cast<const float4*>(g_h + (size_t)warp * 128 + lane * 4);
    acc.x *= sc; acc.y *= sc; acc.z *= sc; acc.w *= sc;
    for (int j = rs; j < re; j++) {
        int s = g_ssrc[j];
        float c = g_scoef[j];
        float4 v = *reinterpret_cast<const float4*>(g_h + (size_t)s * 128 + lane * 4);
        acc.x += v.x * c; acc.y += v.y * c; acc.z += v.z * c; acc.w += v.w * c;
    }
    float4 b = *reinterpret_cast<const float4*>(bias + lane * 4);
    acc.x += b.x; acc.y += b.y; acc.z += b.z; acc.w += b.w;
    if (do_relu) {
        acc.x = fmaxf(acc.x, 0.0f); acc.y = fmaxf(acc.y, 0.0f);
        acc.z = fmaxf(acc.z, 0.0f); acc.w = fmaxf(acc.w, 0.0f);
    }
    *reinterpret_cast<float4*>(out + (size_t)warp * 128 + lane * 4) = acc;
}

__global__ void agg_d64_kernel(const float* __restrict__ bias,
                               float* out_ext, int out_id, int do_relu) {
    int warp = (blockIdx.x * blockDim.x + threadIdx.x) >> 5;
    int lane = threadIdx.x & 31;
    if (warp >= NN) return;
    float* out = out_ext ? out_ext : bufptr(out_id);
    int rs = g_rowptr[warp], re = g_rowptr[warp + 1];
    float di = g_din[warp];
    float sc = di * di;
    float2 acc = *reinterpret_cast<const float2*>(g_h + (size_t)warp * 64 + lane * 2);
    acc.x *= sc; acc.y *= sc;
    for (int j = rs; j < re; j++) {
        int s = g_ssrc[j];
        float c = g_scoef[j];
        float2 v = *reinterpret_cast<const float2*>(g_h + (size_t)s * 64 + lane * 2);
        acc.x += v.x * c; acc.y += v.y * c;
    }
    float2 b = *reinterpret_cast<const float2*>(bias + lane * 2);
    acc.x += b.x; acc.y += b.y;
    if (do_relu) { acc.x = fmaxf(acc.x, 0.0f); acc.y = fmaxf(acc.y, 0.0f); }
    *reinterpret_cast<float2*>(out + (size_t)warp * 64 + lane * 2) = acc;
}

// ---------------- TF32x3 tensor-core GEMM ------------------------------------
// C[N,M] = A[N,K] @ B[K,M] (+bias)(+relu)
// block tile 128x64, 8 warps (4 m x 2 n), warp tile 32x32, BK=16.
#define GBM 128
#define GBN 64
#define GBK 16
#define APAD 4    // As stride 20 floats: frag banks (20m+k)%32 all distinct
#define BPAD 8    // Bs stride 72 floats: frag banks (8k+n)%32 all distinct

__device__ __forceinline__ uint32_t f2tf32(float f) {
    uint32_t u;
    asm("cvt.rna.tf32.f32 %0, %1;" : "=r"(u) : "f"(f));
    return u;
}

__device__ __forceinline__ void mma_tf32(float c[4],
                                         uint32_t a0, uint32_t a1, uint32_t a2, uint32_t a3,
                                         uint32_t b0, uint32_t b1) {
    asm volatile("mma.sync.aligned.m16n8k8.row.col.f32.tf32.tf32.f32 "
                 "{%0,%1,%2,%3}, {%4,%5,%6,%7}, {%8,%9}, {%0,%1,%2,%3};"
                 : "+f"(c[0]), "+f"(c[1]), "+f"(c[2]), "+f"(c[3])
                 : "r"(a0), "r"(a1), "r"(a2), "r"(a3), "r"(b0), "r"(b1));
}

__global__ void __launch_bounds__(256, 2)
gemm_tc_kernel(const float* A_ext, int a_id,
               const float* __restrict__ B,
               const float* __restrict__ bias,
               float* C_ext, int c_id,
               int N, int K, int M, int do_relu) {
    __shared__ float As[GBM][GBK + APAD];
    __shared__ float Bs[GBK][GBN + BPAD];

    const float* A = A_ext ? A_ext : bufptr(a_id);
    float*       C = C_ext ? C_ext : bufptr(c_id);

    int tid  = threadIdx.x;
    int wid  = tid >> 5;
    int lane = tid & 31;
    int wm   = wid & 3;          // warp m index (0..3)
    int wn   = wid >> 2;         // warp n index (0..1)
    int group = lane >> 2;       // 0..7
    int tig   = lane & 3;        // 0..3

    int row0 = blockIdx.y * GBM;
    int col0 = blockIdx.x * GBN;

    float acc[2][4][4];          // [mi][ni][frag]
#pragma unroll
    for (int mi = 0; mi < 2; mi++)
#pragma unroll
        for (int ni = 0; ni < 4; ni++)
#pragma unroll
            for (int q = 0; q < 4; q++) acc[mi][ni][q] = 0.0f;

    for (int k0 = 0; k0 < K; k0 += GBK) {
        // ---- load A tile: 128 x 16 floats = 512 float4, 2 per thread ----
#pragma unroll
        for (int q = 0; q < 2; q++) {
            int f4 = tid * 2 + q;
            int r  = f4 >> 2;
            int c4 = (f4 & 3) * 4;
            int gr = row0 + r;
            float4 v = make_float4(0.f, 0.f, 0.f, 0.f);
            if (gr < N)
                v = *reinterpret_cast<const float4*>(A + (size_t)gr * K + k0 + c4);
            *reinterpret_cast<float4*>(&As[r][c4]) = v;
        }
        // ---- load B tile: 16 x 64 floats = 256 float4, 1 per thread ----
        {
            int r  = tid >> 4;
            int c4 = (tid & 15) * 4;
            float4 v = *reinterpret_cast<const float4*>(B + (size_t)(k0 + r) * M + col0 + c4);
            *reinterpret_cast<float4*>(&Bs[r][c4]) = v;
        }
        __syncthreads();

#pragma unroll
        for (int kk = 0; kk < GBK; kk += 8) {
            // A fragments (hi/lo) for both 16-row tiles
            uint32_t ahi[2][4], alo[2][4];
#pragma unroll
            for (int mi = 0; mi < 2; mi++) {
                int m = wm * 32 + mi * 16 + group;
                float f0 = As[m    ][kk + tig];
                float f1 = As[m + 8][kk + tig];
                float f2 = As[m    ][kk + tig + 4];
                float f3 = As[m + 8][kk + tig + 4];
                ahi[mi][0] = f2tf32(f0); alo[mi][0] = f2tf32(f0 - __uint_as_float(ahi[mi][0]));
                ahi[mi][1] = f2tf32(f1); alo[mi][1] = f2tf32(f1 - __uint_as_float(ahi[mi][1]));
                ahi[mi][2] = f2tf32(f2); alo[mi][2] = f2tf32(f2 - __uint_as_float(ahi[mi][2]));
                ahi[mi][3] = f2tf32(f3); alo[mi][3] = f2tf32(f3 - __uint_as_float(ahi[mi][3]));
            }
#pragma unroll
            for (int ni = 0; ni < 4; ni++) {
                int n = wn * 32 + ni * 8 + group;
                float g0 = Bs[kk + tig    ][n];
                float g1 = Bs[kk + tig + 4][n];
                uint32_t bhi0 = f2tf32(g0), blo0 = f2tf32(g0 - __uint_as_float(bhi0));
                uint32_t bhi1 = f2tf32(g1), blo1 = f2tf32(g1 - __uint_as_float(bhi1));
#pragma unroll
                for (int mi = 0; mi < 2; mi++) {
                    mma_tf32(acc[mi][ni], ahi[mi][0], ahi[mi][1], ahi[mi][2], ahi[mi][3], bhi0, bhi1);
                    mma_tf32(acc[mi][ni], ahi[mi][0], ahi[mi][1], ahi[mi][2], ahi[mi][3], blo0, blo1);
                    mma_tf32(acc[mi][ni], alo[mi][0], alo[mi][1], alo[mi][2], alo[mi][3], bhi0, bhi1);
                }
            }
        }
        __syncthreads();
    }

    // ---- epilogue ----
#pragma unroll
    for (int mi = 0; mi < 2; mi++) {
#pragma unroll
        for (int ni = 0; ni < 4; ni++) {
            int colb = col0 + wn * 32 + ni * 8 + tig * 2;
            float b0 = 0.f, b1 = 0.f;
            if (bias) { b0 = bias[colb]; b1 = bias[colb + 1]; }
#pragma unroll
            for (int half = 0; half < 2; half++) {
                int r = row0 + wm * 32 + mi * 16 + group + half * 8;
                if (r >= N) continue;
                float v0 = acc[mi][ni][half * 2 + 0] + b0;
                float v1 = acc[mi][ni][half * 2 + 1] + b1;
                if (do_relu) { v0 = fmaxf(v0, 0.f); v1 = fmaxf(v1, 0.f); }
                float2 vv = make_float2(v0, v1);
                *reinterpret_cast<float2*>(C + (size_t)r * M + colb) = vv;
            }
        }
    }
}

// ---------------- orchestration ----------------------------------------------
static inline void run_gemm(const float* A_ext, int a_id, const float* B,
                            const float* bias, float* C_ext, int c_id,
                            int n, int K, int M, int relu) {
    dim3 grid(M / GBN, (n + GBM - 1) / GBM);
    gemm_tc_kernel<<<grid, 256>>>(A_ext, a_id, B, bias, C_ext, c_id, n, K, M, relu);
}

static inline void run_agg128(const float* b, float* out_ext, int out_id, int relu) {
    int blocks = (NN + 7) / 8;
    agg_d128_kernel<<<blocks, 256>>>(b, out_ext, out_id, relu);
}

static inline void run_agg64(const float* b, float* out_ext, int out_id, int relu) {
    int blocks = (NN + 7) / 8;
    agg_d64_kernel<<<blocks, 256>>>(b, out_ext, out_id, relu);
}

extern "C" void kernel_launch(void* const* d_in, const int* in_sizes, int n_in,
                              void* d_out, int out_size) {
    const float* x   = (const float*)d_in[0];
    const void*  ei  = d_in[1];
    const float* W1  = (const float*)d_in[2];
    const float* b1  = (const float*)d_in[3];
    const float* W2  = (const float*)d_in[4];
    const float* b2  = (const float*)d_in[5];
    const float* W3  = (const float*)d_in[6];
    const float* b3  = (const float*)d_in[7];
    const float* Wd1 = (const float*)d_in[8];
    const float* bd1 = (const float*)d_in[9];
    const float* Wd2 = (const float*)d_in[10];
    const float* bd2 = (const float*)d_in[11];

    float* z    = (float*)d_out;                     // [N, 64]
    float* xhat = (float*)d_out + (size_t)NN * DE;   // [N, 256]

    // ---- graph preprocessing: dtype convert + CSR build -----------------
    detect_kernel<<<1, 32>>>((const int*)ei);
    zero_cnt_kernel<<<(NN + 255) / 256, 256>>>();
    convert_kernel<<<(2 * EE + 255) / 256, 256>>>(ei);
    dinv_kernel<<<(NN + 255) / 256, 256>>>();
    scan1_kernel<<<NB, 1024>>>();
    scan2_kernel<<<1, 32>>>();
    scan3_kernel<<<(NN + 255) / 256, 256>>>();
    curinit_kernel<<<(NN + 255) / 256, 256>>>();
    fill_csr_kernel<<<(EE + 255) / 256, 256>>>();

    // ---- layer 1: h1 = relu(gcn(x, W1, b1)) -----------------------------
    run_gemm(x, -1, W1, nullptr, nullptr, 0, NN, DIN, DH, 0);   // g_h = x@W1
    run_agg128(b1, nullptr, 2, 1);                              // -> g_h1

    // ---- layer 2: h2 = relu(gcn(h1, W2, b2)) ----------------------------
    run_gemm(nullptr, 2, W2, nullptr, nullptr, 0, NN, DH, DH, 0);
    run_agg128(b2, nullptr, 2, 1);

    // ---- layer 3: z = gcn(h2, W3, b3) -----------------------------------
    run_gemm(nullptr, 2, W3, nullptr, nullptr, 0, NN, DH, DE, 0);
    run_agg64(b3, z, -1, 0);

    // ---- decoder: x_hat = relu(z@Wd1+bd1)@Wd2 + bd2 ---------------------
    run_gemm(z, -1, Wd1, bd1, nullptr, 2, NN, DE, DH, 1);
    run_gemm(nullptr, 2, Wd2, bd2, xhat, -1, NN, DH, DIN, 0);
}

// round 7
// speedup vs baseline: 2.6329x; 1.0408x over previous
#include <cuda_runtime.h>
#include <math.h>
#include <stdint.h>

#define NN 100000
#define EE 600000
#define DIN 256
#define DH  128
#define DE  64
#define NB  ((NN + 1023) / 1024)

// ---------------- scratch (static device globals; no allocation) ------------
__device__ float g_h   [(size_t)NN * DH];  // GEMM output (pre-aggregation)
__device__ float g_h1  [(size_t)NN * DH];  // layer activation buffer
__device__ float g_din [NN];               // 1/sqrt(deg+1)
__device__ int   g_cnt [NN];               // in-degree counts
__device__ int   g_rowptr[NN + 1];         // CSR row pointers (by dst)
__device__ int   g_cur [NN];               // placement cursors
__device__ int   g_bsum[NB];               // scan block sums
__device__ int   g_ssrc [EE];              // CSR: src node per sorted edge
__device__ float g_scoef[EE];              // CSR: dinv[src]*dinv[dst]
__device__ int   g_src[EE];
__device__ int   g_dst[EE];
__device__ int   g_is64;

__device__ __forceinline__ float* bufptr(int id) {
    switch (id) {
        case 0:  return g_h;
        default: return g_h1;
    }
}

// ---------------- edge-index dtype detection + conversion -------------------
__global__ void detect_kernel(const int* __restrict__ w) {
    if (threadIdx.x == 0 && blockIdx.x == 0) {
        int is64 = 1;
        for (int i = 1; i < 128; i += 2)
            if (w[i] != 0) { is64 = 0; break; }
        g_is64 = is64;
    }
}

// convert + clamp + count in-degree (dst side) in one pass
__global__ void convert_kernel(const void* __restrict__ ei) {
    int e = blockIdx.x * blockDim.x + threadIdx.x;
    if (e >= 2 * EE) return;
    int v;
    if (g_is64) v = (int)((const long long*)ei)[e];
    else        v = ((const int*)ei)[e];
    v = max(0, min(NN - 1, v));
    if (e < EE) g_src[e] = v;
    else        { g_dst[e - EE] = v; atomicAdd(&g_cnt[v], 1); }
}

// ---------------- CSR construction -------------------------------------------
__global__ void zero_cnt_kernel() {
    int i = blockIdx.x * blockDim.x + threadIdx.x;
    if (i < NN) g_cnt[i] = 0;
}

__global__ void dinv_kernel() {
    int i = blockIdx.x * blockDim.x + threadIdx.x;
    if (i < NN) g_din[i] = rsqrtf((float)g_cnt[i] + 1.0f);
}

__global__ void scan1_kernel() {
    __shared__ int s[1024];
    int i = blockIdx.x * 1024 + threadIdx.x;
    int v = (i < NN) ? g_cnt[i] : 0;
    s[threadIdx.x] = v;
    __syncthreads();
    for (int off = 1; off < 1024; off <<= 1) {
        int t = (threadIdx.x >= off) ? s[threadIdx.x - off] : 0;
        __syncthreads();
        s[threadIdx.x] += t;
        __syncthreads();
    }
    if (i < NN) g_rowptr[i + 1] = s[threadIdx.x];
    if (threadIdx.x == 1023) g_bsum[blockIdx.x] = s[1023];
}

__global__ void scan2_kernel() {
    if (threadIdx.x == 0 && blockIdx.x == 0) {
        int run = 0;
        for (int b = 0; b < NB; b++) { int t = g_bsum[b]; g_bsum[b] = run; run += t; }
        g_rowptr[0] = 0;
    }
}

__global__ void scan3_kernel() {
    int i = blockIdx.x * blockDim.x + threadIdx.x;
    if (i < NN) g_rowptr[i + 1] += g_bsum[i >> 10];
}

__global__ void curinit_kernel() {
    int i = blockIdx.x * blockDim.x + threadIdx.x;
    if (i < NN) g_cur[i] = g_rowptr[i];
}

__global__ void fill_csr_kernel() {
    int e = blockIdx.x * blockDim.x + threadIdx.x;
    if (e >= EE) return;
    int s = g_src[e];
    int d = g_dst[e];
    int slot = atomicAdd(&g_cur[d], 1);
    g_ssrc[slot]  = s;
    g_scoef[slot] = g_din[s] * g_din[d];
}

// ---------------- fused aggregation (gather + self-loop + bias + relu) -------
__global__ void agg_d128_kernel(const float* __restrict__ bias,
                                float* out_ext, int out_id, int do_relu) {
    int warp = (blockIdx.x * blockDim.x + threadIdx.x) >> 5;
    int lane = threadIdx.x & 31;
    if (warp >= NN) return;
    float* out = out_ext ? out_ext : bufptr(out_id);
    int rs = g_rowptr[warp], re = g_rowptr[warp + 1];
    float di = g_din[warp];
    float sc = di * di;
    float4 acc = *reinterpret_cast<const float4*>(g_h + (size_t)warp * 128 + lane * 4);
    acc.x *= sc; acc.y *= sc; acc.z *= sc; acc.w *= sc;
    for (int j = rs; j < re; j++) {
        int s = g_ssrc[j];
        float c = g_scoef[j];
        float4 v = *reinterpret_cast<const float4*>(g_h + (size_t)s * 128 + lane * 4);
        acc.x += v.x * c; acc.y += v.y * c; acc.z += v.z * c; acc.w += v.w * c;
    }
    float4 b = *reinterpret_cast<const float4*>(bias + lane * 4);
    acc.x += b.x; acc.y += b.y; acc.z += b.z; acc.w += b.w;
    if (do_relu) {
        acc.x = fmaxf(acc.x, 0.0f); acc.y = fmaxf(acc.y, 0.0f);
        acc.z = fmaxf(acc.z, 0.0f); acc.w = fmaxf(acc.w, 0.0f);
    }
    *reinterpret_cast<float4*>(out + (size_t)warp * 128 + lane * 4) = acc;
}

__global__ void agg_d64_kernel(const float* __restrict__ bias,
                               float* out_ext, int out_id, int do_relu) {
    int warp = (blockIdx.x * blockDim.x + threadIdx.x) >> 5;
    int lane = threadIdx.x & 31;
    if (warp >= NN) return;
    float* out = out_ext ? out_ext : bufptr(out_id);
    int rs = g_rowptr[warp], re = g_rowptr[warp + 1];
    float di = g_din[warp];
    float sc = di * di;
    float2 acc = *reinterpret_cast<const float2*>(g_h + (size_t)warp * 64 + lane * 2);
    acc.x *= sc; acc.y *= sc;
    for (int j = rs; j < re; j++) {
        int s = g_ssrc[j];
        float c = g_scoef[j];
        float2 v = *reinterpret_cast<const float2*>(g_h + (size_t)s * 64 + lane * 2);
        acc.x += v.x * c; acc.y += v.y * c;
    }
    float2 b = *reinterpret_cast<const float2*>(bias + lane * 2);
    acc.x += b.x; acc.y += b.y;
    if (do_relu) { acc.x = fmaxf(acc.x, 0.0f); acc.y = fmaxf(acc.y, 0.0f); }
    *reinterpret_cast<float2*>(out + (size_t)warp * 64 + lane * 2) = acc;
}

// ---------------- TF32x3 tensor-core GEMM ------------------------------------
// C[N,M] = A[N,K] @ B[K,M] (+bias)(+relu)
// block tile 128x64, 8 warps (4 m x 2 n), warp tile 32x32, BK=16.
// hi/lo tf32 split precomputed into smem at tile-load; register double-buffer.
#define GBM 128
#define GBN 64
#define GBK 16
#define APAD 4    // As stride 20: frag banks (20m+k)%32 all distinct
#define BPAD 8    // Bs stride 72: frag banks (8k+n)%32 all distinct

__device__ __forceinline__ uint32_t f2tf32(float f) {
    uint32_t u;
    asm("cvt.rna.tf32.f32 %0, %1;" : "=r"(u) : "f"(f));
    return u;
}

__device__ __forceinline__ void split1(float f, uint32_t& h, uint32_t& l) {
    h = f2tf32(f);
    l = f2tf32(f - __uint_as_float(h));
}

__device__ __forceinline__ void split4(const float4& v, uint4& h, uint4& l) {
    split1(v.x, h.x, l.x);
    split1(v.y, h.y, l.y);
    split1(v.z, h.z, l.z);
    split1(v.w, h.w, l.w);
}

__device__ __forceinline__ void mma_tf32(float c[4],
                                         uint32_t a0, uint32_t a1, uint32_t a2, uint32_t a3,
                                         uint32_t b0, uint32_t b1) {
    asm volatile("mma.sync.aligned.m16n8k8.row.col.f32.tf32.tf32.f32 "
                 "{%0,%1,%2,%3}, {%4,%5,%6,%7}, {%8,%9}, {%0,%1,%2,%3};"
                 : "+f"(c[0]), "+f"(c[1]), "+f"(c[2]), "+f"(c[3])
                 : "r"(a0), "r"(a1), "r"(a2), "r"(a3), "r"(b0), "r"(b1));
}

__global__ void __launch_bounds__(256, 2)
gemm_tc_kernel(const float* A_ext, int a_id,
               const float* __restrict__ B,
               const float* __restrict__ bias,
               float* C_ext, int c_id,
               int N, int K, int M, int do_relu) {
    __shared__ uint32_t AsH[GBM][GBK + APAD];
    __shared__ uint32_t AsL[GBM][GBK + APAD];
    __shared__ uint32_t BsH[GBK][GBN + BPAD];
    __shared__ uint32_t BsL[GBK][GBN + BPAD];

    const float* A = A_ext ? A_ext : bufptr(a_id);
    float*       C = C_ext ? C_ext : bufptr(c_id);

    int tid  = threadIdx.x;
    int wid  = tid >> 5;
    int lane = tid & 31;
    int wm   = wid & 3;
    int wn   = wid >> 2;
    int group = lane >> 2;       // 0..7
    int tig   = lane & 3;        // 0..3

    int row0 = blockIdx.y * GBM;
    int col0 = blockIdx.x * GBN;

    float acc[2][4][4];
#pragma unroll
    for (int mi = 0; mi < 2; mi++)
#pragma unroll
        for (int ni = 0; ni < 4; ni++)
#pragma unroll
            for (int q = 0; q < 4; q++) acc[mi][ni][q] = 0.0f;

    auto loadTile = [&](int k0, float4 (&pa)[2], float4& pb) {
#pragma unroll
        for (int q = 0; q < 2; q++) {
            int f4 = tid * 2 + q;
            int r  = f4 >> 2;
            int c4 = (f4 & 3) * 4;
            int gr = row0 + r;
            pa[q] = (gr < N)
                  ? *reinterpret_cast<const float4*>(A + (size_t)gr * K + k0 + c4)
                  : make_float4(0.f, 0.f, 0.f, 0.f);
        }
        {
            int r  = tid >> 4;
            int c4 = (tid & 15) * 4;
            pb = *reinterpret_cast<const float4*>(B + (size_t)(k0 + r) * M + col0 + c4);
        }
    };

    auto storeTile = [&](const float4 (&pa)[2], const float4& pb) {
#pragma unroll
        for (int q = 0; q < 2; q++) {
            int f4 = tid * 2 + q;
            int r  = f4 >> 2;
            int c4 = (f4 & 3) * 4;
            uint4 h, l;
            split4(pa[q], h, l);
            *reinterpret_cast<uint4*>(&AsH[r][c4]) = h;
            *reinterpret_cast<uint4*>(&AsL[r][c4]) = l;
        }
        {
            int r  = tid >> 4;
            int c4 = (tid & 15) * 4;
            uint4 h, l;
            split4(pb, h, l);
            *reinterpret_cast<uint4*>(&BsH[r][c4]) = h;
            *reinterpret_cast<uint4*>(&BsL[r][c4]) = l;
        }
    };

    auto compute = [&]() {
#pragma unroll
        for (int kk = 0; kk < GBK; kk += 8) {
            uint32_t ahi[2][4], alo[2][4];
#pragma unroll
            for (int mi = 0; mi < 2; mi++) {
                int m = wm * 32 + mi * 16 + group;
                ahi[mi][0] = AsH[m    ][kk + tig];
                ahi[mi][1] = AsH[m + 8][kk + tig];
                ahi[mi][2] = AsH[m    ][kk + tig + 4];
                ahi[mi][3] = AsH[m + 8][kk + tig + 4];
                alo[mi][0] = AsL[m    ][kk + tig];
                alo[mi][1] = AsL[m + 8][kk + tig];
                alo[mi][2] = AsL[m    ][kk + tig + 4];
                alo[mi][3] = AsL[m + 8][kk + tig + 4];
            }
#pragma unroll
            for (int ni = 0; ni < 4; ni++) {
                int n = wn * 32 + ni * 8 + group;
                uint32_t bhi0 = BsH[kk + tig    ][n];
                uint32_t bhi1 = BsH[kk + tig + 4][n];
                uint32_t blo0 = BsL[kk + tig    ][n];
                uint32_t blo1 = BsL[kk + tig + 4][n];
#pragma unroll
                for (int mi = 0; mi < 2; mi++) {
                    mma_tf32(acc[mi][ni], ahi[mi][0], ahi[mi][1], ahi[mi][2], ahi[mi][3], bhi0, bhi1);
                    mma_tf32(acc[mi][ni], ahi[mi][0], ahi[mi][1], ahi[mi][2], ahi[mi][3], blo0, blo1);
                    mma_tf32(acc[mi][ni], alo[mi][0], alo[mi][1], alo[mi][2], alo[mi][3], bhi0, bhi1);
                }
            }
        }
    };

    // prologue: tile 0
    float4 pa[2]; float4 pb;
    loadTile(0, pa, pb);
    storeTile(pa, pb);
    __syncthreads();

    // main loop with register prefetch
    for (int k0 = GBK; k0 < K; k0 += GBK) {
        float4 na[2]; float4 nb;
        loadTile(k0, na, nb);        // prefetch next tile (gmem -> regs)
        compute();                   // compute current tile from smem
        __syncthreads();
        storeTile(na, nb);           // split + store prefetched tile
        __syncthreads();
    }
    compute();                       // last tile

    // ---- epilogue ----
#pragma unroll
    for (int mi = 0; mi < 2; mi++) {
#pragma unroll
        for (int ni = 0; ni < 4; ni++) {
            int colb = col0 + wn * 32 + ni * 8 + tig * 2;
            float b0 = 0.f, b1 = 0.f;
            if (bias) { b0 = bias[colb]; b1 = bias[colb + 1]; }
#pragma unroll
            for (int half = 0; half < 2; half++) {
                int r = row0 + wm * 32 + mi * 16 + group + half * 8;
                if (r >= N) continue;
                float v0 = acc[mi][ni][half * 2 + 0] + b0;
                float v1 = acc[mi][ni][half * 2 + 1] + b1;
                if (do_relu) { v0 = fmaxf(v0, 0.f); v1 = fmaxf(v1, 0.f); }
                float2 vv = make_float2(v0, v1);
                *reinterpret_cast<float2*>(C + (size_t)r * M + colb) = vv;
            }
        }
    }
}

// ---------------- orchestration ----------------------------------------------
static inline void run_gemm(const float* A_ext, int a_id, const float* B,
                            const float* bias, float* C_ext, int c_id,
                            int n, int K, int M, int relu) {
    dim3 grid(M / GBN, (n + GBM - 1) / GBM);
    gemm_tc_kernel<<<grid, 256>>>(A_ext, a_id, B, bias, C_ext, c_id, n, K, M, relu);
}

static inline void run_agg128(const float* b, float* out_ext, int out_id, int relu) {
    int blocks = (NN + 7) / 8;
    agg_d128_kernel<<<blocks, 256>>>(b, out_ext, out_id, relu);
}

static inline void run_agg64(const float* b, float* out_ext, int out_id, int relu) {
    int blocks = (NN + 7) / 8;
    agg_d64_kernel<<<blocks, 256>>>(b, out_ext, out_id, relu);
}

extern "C" void kernel_launch(void* const* d_in, const int* in_sizes, int n_in,
                              void* d_out, int out_size) {
    const float* x   = (const float*)d_in[0];
    const void*  ei  = d_in[1];
    const float* W1  = (const float*)d_in[2];
    const float* b1  = (const float*)d_in[3];
    const float* W2  = (const float*)d_in[4];
    const float* b2  = (const float*)d_in[5];
    const float* W3  = (const float*)d_in[6];
    const float* b3  = (const float*)d_in[7];
    const float* Wd1 = (const float*)d_in[8];
    const float* bd1 = (const float*)d_in[9];
    const float* Wd2 = (const float*)d_in[10];
    const float* bd2 = (const float*)d_in[11];

    float* z    = (float*)d_out;                     // [N, 64]
    float* xhat = (float*)d_out + (size_t)NN * DE;   // [N, 256]

    // ---- graph preprocessing: dtype convert + CSR build -----------------
    detect_kernel<<<1, 32>>>((const int*)ei);
    zero_cnt_kernel<<<(NN + 255) / 256, 256>>>();
    convert_kernel<<<(2 * EE + 255) / 256, 256>>>(ei);
    dinv_kernel<<<(NN + 255) / 256, 256>>>();
    scan1_kernel<<<NB, 1024>>>();
    scan2_kernel<<<1, 32>>>();
    scan3_kernel<<<(NN + 255) / 256, 256>>>();
    curinit_kernel<<<(NN + 255) / 256, 256>>>();
    fill_csr_kernel<<<(EE + 255) / 256, 256>>>();

    // ---- layer 1: h1 = relu(gcn(x, W1, b1)) -----------------------------
    run_gemm(x, -1, W1, nullptr, nullptr, 0, NN, DIN, DH, 0);   // g_h = x@W1
    run_agg128(b1, nullptr, 2, 1);                              // -> g_h1

    // ---- layer 2: h2 = relu(gcn(h1, W2, b2)) ----------------------------
    run_gemm(nullptr, 2, W2, nullptr, nullptr, 0, NN, DH, DH, 0);
    run_agg128(b2, nullptr, 2, 1);

    // ---- layer 3: z = gcn(h2, W3, b3) -----------------------------------
    run_gemm(nullptr, 2, W3, nullptr, nullptr, 0, NN, DH, DE, 0);
    run_agg64(b3, z, -1, 0);

    // ---- decoder: x_hat = relu(z@Wd1+bd1)@Wd2 + bd2 ---------------------
    run_gemm(z, -1, Wd1, bd1, nullptr, 2, NN, DE, DH, 1);
    run_gemm(nullptr, 2, Wd2, bd2, xhat, -1, NN, DH, DIN, 0);
}

// round 9
// speedup vs baseline: 2.7020x; 1.0262x over previous
#include <cuda_runtime.h>
#include <math.h>
#include <stdint.h>

#define NN 100000
#define EE 600000
#define DIN 256
#define DH  128
#define DE  64
#define NB  ((NN + 1023) / 1024)

// ---------------- scratch (static device globals; no allocation) ------------
__device__ float g_h   [(size_t)NN * DH];  // GEMM output (pre-aggregation)
__device__ float g_h1  [(size_t)NN * DH];  // layer activation buffer
__device__ float g_din [NN];               // 1/sqrt(deg+1)
__device__ int   g_cnt [NN];               // in-degree counts
__device__ int   g_rowptr[NN + 1];         // CSR row pointers (by dst)
__device__ int   g_cur [NN];               // placement cursors
__device__ int   g_bsum[NB];               // scan block sums
__device__ int   g_ssrc [EE];              // CSR: src node per sorted edge
__device__ float g_scoef[EE];              // CSR: dinv[src]*dinv[dst]
__device__ int   g_src[EE];
__device__ int   g_dst[EE];
__device__ int   g_is64;

__device__ __forceinline__ float* bufptr(int id) {
    switch (id) {
        case 0:  return g_h;
        default: return g_h1;
    }
}

// ---------------- edge-index dtype detection + conversion -------------------
__global__ void detect_kernel(const int* __restrict__ w) {
    if (threadIdx.x == 0 && blockIdx.x == 0) {
        int is64 = 1;
        for (int i = 1; i < 128; i += 2)
            if (w[i] != 0) { is64 = 0; break; }
        g_is64 = is64;
    }
}

// convert + clamp + count in-degree (dst side) in one pass
__global__ void convert_kernel(const void* __restrict__ ei) {
    int e = blockIdx.x * blockDim.x + threadIdx.x;
    if (e >= 2 * EE) return;
    int v;
    if (g_is64) v = (int)((const long long*)ei)[e];
    else        v = ((const int*)ei)[e];
    v = max(0, min(NN - 1, v));
    if (e < EE) g_src[e] = v;
    else        { g_dst[e - EE] = v; atomicAdd(&g_cnt[v], 1); }
}

// ---------------- CSR construction -------------------------------------------
__global__ void zero_cnt_kernel() {
    int i = blockIdx.x * blockDim.x + threadIdx.x;
    if (i < NN) g_cnt[i] = 0;
}

__global__ void dinv_kernel() {
    int i = blockIdx.x * blockDim.x + threadIdx.x;
    if (i < NN) g_din[i] = rsqrtf((float)g_cnt[i] + 1.0f);
}

__global__ void scan1_kernel() {
    __shared__ int s[1024];
    int i = blockIdx.x * 1024 + threadIdx.x;
    int v = (i < NN) ? g_cnt[i] : 0;
    s[threadIdx.x] = v;
    __syncthreads();
    for (int off = 1; off < 1024; off <<= 1) {
        int t = (threadIdx.x >= off) ? s[threadIdx.x - off] : 0;
        __syncthreads();
        s[threadIdx.x] += t;
        __syncthreads();
    }
    if (i < NN) g_rowptr[i + 1] = s[threadIdx.x];
    if (threadIdx.x == 1023) g_bsum[blockIdx.x] = s[1023];
}

__global__ void scan2_kernel() {
    if (threadIdx.x == 0 && blockIdx.x == 0) {
        int run = 0;
        for (int b = 0; b < NB; b++) { int t = g_bsum[b]; g_bsum[b] = run; run += t; }
        g_rowptr[0] = 0;
    }
}

__global__ void scan3_kernel() {
    int i = blockIdx.x * blockDim.x + threadIdx.x;
    if (i < NN) g_rowptr[i + 1] += g_bsum[i >> 10];
}

__global__ void curinit_kernel() {
    int i = blockIdx.x * blockDim.x + threadIdx.x;
    if (i < NN) g_cur[i] = g_rowptr[i];
}

__global__ void fill_csr_kernel() {
    int e = blockIdx.x * blockDim.x + threadIdx.x;
    if (e >= EE) return;
    int s = g_src[e];
    int d = g_dst[e];
    int slot = atomicAdd(&g_cur[d], 1);
    g_ssrc[slot]  = s;
    g_scoef[slot] = g_din[s] * g_din[d];
}

// ---------------- fused aggregation (gather + self-loop + bias + relu) -------
__global__ void agg_d128_kernel(const float* __restrict__ bias,
                                float* out_ext, int out_id, int do_relu) {
    int warp = (blockIdx.x * blockDim.x + threadIdx.x) >> 5;
    int lane = threadIdx.x & 31;
    if (warp >= NN) return;
    float* out = out_ext ? out_ext : bufptr(out_id);
    int rs = g_rowptr[warp], re = g_rowptr[warp + 1];
    float di = g_din[warp];
    float sc = di * di;
    float4 acc = *reinterpret_cast<const float4*>(g_h + (size_t)warp * 128 + lane * 4);
    acc.x *= sc; acc.y *= sc; acc.z *= sc; acc.w *= sc;
    for (int j = rs; j < re; j++) {
        int s = g_ssrc[j];
        float c = g_scoef[j];
        float4 v = *reinterpret_cast<const float4*>(g_h + (size_t)s * 128 + lane * 4);
        acc.x += v.x * c; acc.y += v.y * c; acc.z += v.z * c; acc.w += v.w * c;
    }
    float4 b = *reinterpret_cast<const float4*>(bias + lane * 4);
    acc.x += b.x; acc.y += b.y; acc.z += b.z; acc.w += b.w;
    if (do_relu) {
        acc.x = fmaxf(acc.x, 0.0f); acc.y = fmaxf(acc.y, 0.0f);
        acc.z = fmaxf(acc.z, 0.0f); acc.w = fmaxf(acc.w, 0.0f);
    }
    *reinterpret_cast<float4*>(out + (size_t)warp * 128 + lane * 4) = acc;
}

__global__ void agg_d64_kernel(const float* __restrict__ bias,
                               float* out_ext, int out_id, int do_relu) {
    int warp = (blockIdx.x * blockDim.x + threadIdx.x) >> 5;
    int lane = threadIdx.x & 31;
    if (warp >= NN) return;
    float* out = out_ext ? out_ext : bufptr(out_id);
    int rs = g_rowptr[warp], re = g_rowptr[warp + 1];
    float di = g_din[warp];
    float sc = di * di;
    float2 acc = *reinterpret_cast<const float2*>(g_h + (size_t)warp * 64 + lane * 2);
    acc.x *= sc; acc.y *= sc;
    for (int j = rs; j < re; j++) {
        int s = g_ssrc[j];
        float c = g_scoef[j];
        float2 v = *reinterpret_cast<const float2*>(g_h + (size_t)s * 64 + lane * 2);
        acc.x += v.x * c; acc.y += v.y * c;
    }
    float2 b = *reinterpret_cast<const float2*>(bias + lane * 2);
    acc.x += b.x; acc.y += b.y;
    if (do_relu) { acc.x = fmaxf(acc.x, 0.0f); acc.y = fmaxf(acc.y, 0.0f); }
    *reinterpret_cast<float2*>(out + (size_t)warp * 64 + lane * 2) = acc;
}

// ---------------- TF32x3 tensor-core GEMM ------------------------------------
// C[N,M] = A[N,K] @ B[K,M] (+bias)(+relu)
// block tile 128x64, 8 warps (4 m x 2 n), warp tile 32x32, BK=16.
// hi/lo tf32 split precomputed into smem at tile-load; register double-buffer.
// Inner loop ordered combo-outermost (HH all tiles, HL all tiles, LH all tiles)
// so each accumulator is reused at distance 8 mmas -> RAW latency hidden.
#define GBM 128
#define GBN 64
#define GBK 16
#define APAD 4    // As stride 20: frag banks (20m+k)%32 all distinct
#define BPAD 8    // Bs stride 72: frag banks (8k+n)%32 all distinct

__device__ __forceinline__ uint32_t f2tf32(float f) {
    uint32_t u;
    asm("cvt.rna.tf32.f32 %0, %1;" : "=r"(u) : "f"(f));
    return u;
}

__device__ __forceinline__ void split1(float f, uint32_t& h, uint32_t& l) {
    h = f2tf32(f);
    l = f2tf32(f - __uint_as_float(h));
}

__device__ __forceinline__ void split4(const float4& v, uint4& h, uint4& l) {
    split1(v.x, h.x, l.x);
    split1(v.y, h.y, l.y);
    split1(v.z, h.z, l.z);
    split1(v.w, h.w, l.w);
}

// non-volatile, no clobbers: lets the compiler/ptxas interleave independent mmas
__device__ __forceinline__ void mma_tf32(float c[4],
                                         const uint32_t a[4],
                                         uint32_t b0, uint32_t b1) {
    asm("mma.sync.aligned.m16n8k8.row.col.f32.tf32.tf32.f32 "
        "{%0,%1,%2,%3}, {%4,%5,%6,%7}, {%8,%9}, {%0,%1,%2,%3};"
        : "+f"(c[0]), "+f"(c[1]), "+f"(c[2]), "+f"(c[3])
        : "r"(a[0]), "r"(a[1]), "r"(a[2]), "r"(a[3]), "r"(b0), "r"(b1));
}

__global__ void __launch_bounds__(256, 2)
gemm_tc_kernel(const float* A_ext, int a_id,
               const float* __restrict__ B,
               const float* __restrict__ bias,
               float* C_ext, int c_id,
               int N, int K, int M, int do_relu) {
    __shared__ uint32_t AsH[GBM][GBK + APAD];
    __shared__ uint32_t AsL[GBM][GBK + APAD];
    __shared__ uint32_t BsH[GBK][GBN + BPAD];
    __shared__ uint32_t BsL[GBK][GBN + BPAD];

    const float* A = A_ext ? A_ext : bufptr(a_id);
    float*       C = C_ext ? C_ext : bufptr(c_id);

    int tid  = threadIdx.x;
    int wid  = tid >> 5;
    int lane = tid & 31;
    int wm   = wid & 3;
    int wn   = wid >> 2;
    int group = lane >> 2;       // 0..7
    int tig   = lane & 3;        // 0..3

    int row0 = blockIdx.y * GBM;
    int col0 = blockIdx.x * GBN;

    float acc[2][4][4];
#pragma unroll
    for (int mi = 0; mi < 2; mi++)
#pragma unroll
        for (int ni = 0; ni < 4; ni++)
#pragma unroll
            for (int q = 0; q < 4; q++) acc[mi][ni][q] = 0.0f;

    auto loadTile = [&](int k0, float4 (&pa)[2], float4& pb) {
#pragma unroll
        for (int q = 0; q < 2; q++) {
            int f4 = tid * 2 + q;
            int r  = f4 >> 2;
            int c4 = (f4 & 3) * 4;
            int gr = row0 + r;
            pa[q] = (gr < N)
                  ? *reinterpret_cast<const float4*>(A + (size_t)gr * K + k0 + c4)
                  : make_float4(0.f, 0.f, 0.f, 0.f);
        }
        {
            int r  = tid >> 4;
            int c4 = (tid & 15) * 4;
            pb = *reinterpret_cast<const float4*>(B + (size_t)(k0 + r) * M + col0 + c4);
        }
    };

    auto storeTile = [&](const float4 (&pa)[2], const float4& pb) {
#pragma unroll
        for (int q = 0; q < 2; q++) {
            int f4 = tid * 2 + q;
            int r  = f4 >> 2;
            int c4 = (f4 & 3) * 4;
            uint4 h, l;
            split4(pa[q], h, l);
            *reinterpret_cast<uint4*>(&AsH[r][c4]) = h;
            *reinterpret_cast<uint4*>(&AsL[r][c4]) = l;
        }
        {
            int r  = tid >> 4;
            int c4 = (tid & 15) * 4;
            uint4 h, l;
            split4(pb, h, l);
            *reinterpret_cast<uint4*>(&BsH[r][c4]) = h;
            *reinterpret_cast<uint4*>(&BsL[r][c4]) = l;
        }
    };

    auto compute = [&]() {
#pragma unroll
        for (int kk = 0; kk < GBK; kk += 8) {
            uint32_t ahi[2][4], alo[2][4];
            uint32_t bhi[4][2], blo[4][2];
#pragma unroll
            for (int mi = 0; mi < 2; mi++) {
                int m = wm * 32 + mi * 16 + group;
                ahi[mi][0] = AsH[m    ][kk + tig];
                ahi[mi][1] = AsH[m + 8][kk + tig];
                ahi[mi][2] = AsH[m    ][kk + tig + 4];
                ahi[mi][3] = AsH[m + 8][kk + tig + 4];
                alo[mi][0] = AsL[m    ][kk + tig];
                alo[mi][1] = AsL[m + 8][kk + tig];
                alo[mi][2] = AsL[m    ][kk + tig + 4];
                alo[mi][3] = AsL[m + 8][kk + tig + 4];
            }
#pragma unroll
            for (int ni = 0; ni < 4; ni++) {
                int n = wn * 32 + ni * 8 + group;
                bhi[ni][0] = BsH[kk + tig    ][n];
                bhi[ni][1] = BsH[kk + tig + 4][n];
                blo[ni][0] = BsL[kk + tig    ][n];
                blo[ni][1] = BsL[kk + tig + 4][n];
            }
            // pass 1: HH over all 8 independent accumulators
#pragma unroll
            for (int ni = 0; ni < 4; ni++)
#pragma unroll
                for (int mi = 0; mi < 2; mi++)
                    mma_tf32(acc[mi][ni], ahi[mi], bhi[ni][0], bhi[ni][1]);
            // pass 2: HL
#pragma unroll
            for (int ni = 0; ni < 4; ni++)
#pragma unroll
                for (int mi = 0; mi < 2; mi++)
                    mma_tf32(acc[mi][ni], ahi[mi], blo[ni][0], blo[ni][1]);
            // pass 3: LH
#pragma unroll
            for (int ni = 0; ni < 4; ni++)
#pragma unroll
                for (int mi = 0; mi < 2; mi++)
                    mma_tf32(acc[mi][ni], alo[mi], bhi[ni][0], bhi[ni][1]);
        }
    };

    // prologue: tile 0
    float4 pa[2]; float4 pb;
    loadTile(0, pa, pb);
    storeTile(pa, pb);
    __syncthreads();

    // main loop with register prefetch
    for (int k0 = GBK; k0 < K; k0 += GBK) {
        float4 na[2]; float4 nb;
        loadTile(k0, na, nb);        // prefetch next tile (gmem -> regs)
        compute();                   // compute current tile from smem
        __syncthreads();
        storeTile(na, nb);           // split + store prefetched tile
        __syncthreads();
    }
    compute();                       // last tile

    // ---- epilogue ----
#pragma unroll
    for (int mi = 0; mi < 2; mi++) {
#pragma unroll
        for (int ni = 0; ni < 4; ni++) {
            int colb = col0 + wn * 32 + ni * 8 + tig * 2;
            float b0 = 0.f, b1 = 0.f;
            if (bias) { b0 = bias[colb]; b1 = bias[colb + 1]; }
#pragma unroll
            for (int half = 0; half < 2; half++) {
                int r = row0 + wm * 32 + mi * 16 + group + half * 8;
                if (r >= N) continue;
                float v0 = acc[mi][ni][half * 2 + 0] + b0;
                float v1 = acc[mi][ni][half * 2 + 1] + b1;
                if (do_relu) { v0 = fmaxf(v0, 0.f); v1 = fmaxf(v1, 0.f); }
                float2 vv = make_float2(v0, v1);
                *reinterpret_cast<float2*>(C + (size_t)r * M + colb) = vv;
            }
        }
    }
}

// ---------------- orchestration ----------------------------------------------
static inline void run_gemm(const float* A_ext, int a_id, const float* B,
                            const float* bias, float* C_ext, int c_id,
                            int n, int K, int M, int relu) {
    dim3 grid(M / GBN, (n + GBM - 1) / GBM);
    gemm_tc_kernel<<<grid, 256>>>(A_ext, a_id, B, bias, C_ext, c_id, n, K, M, relu);
}

static inline void run_agg128(const float* b, float* out_ext, int out_id, int relu) {
    int blocks = (NN + 7) / 8;
    agg_d128_kernel<<<blocks, 256>>>(b, out_ext, out_id, relu);
}

static inline void run_agg64(const float* b, float* out_ext, int out_id, int relu) {
    int blocks = (NN + 7) / 8;
    agg_d64_kernel<<<blocks, 256>>>(b, out_ext, out_id, relu);
}

extern "C" void kernel_launch(void* const* d_in, const int* in_sizes, int n_in,
                              void* d_out, int out_size) {
    const float* x   = (const float*)d_in[0];
    const void*  ei  = d_in[1];
    const float* W1  = (const float*)d_in[2];
    const float* b1  = (const float*)d_in[3];
    const float* W2  = (const float*)d_in[4];
    const float* b2  = (const float*)d_in[5];
    const float* W3  = (const float*)d_in[6];
    const float* b3  = (const float*)d_in[7];
    const float* Wd1 = (const float*)d_in[8];
    const float* bd1 = (const float*)d_in[9];
    const float* Wd2 = (const float*)d_in[10];
    const float* bd2 = (const float*)d_in[11];

    float* z    = (float*)d_out;                     // [N, 64]
    float* xhat = (float*)d_out + (size_t)NN * DE;   // [N, 256]

    // ---- graph preprocessing: dtype convert + CSR build -----------------
    detect_kernel<<<1, 32>>>((const int*)ei);
    zero_cnt_kernel<<<(NN + 255) / 256, 256>>>();
    convert_kernel<<<(2 * EE + 255) / 256, 256>>>(ei);
    dinv_kernel<<<(NN + 255) / 256, 256>>>();
    scan1_kernel<<<NB, 1024>>>();
    scan2_kernel<<<1, 32>>>();
    scan3_kernel<<<(NN + 255) / 256, 256>>>();
    curinit_kernel<<<(NN + 255) / 256, 256>>>();
    fill_csr_kernel<<<(EE + 255) / 256, 256>>>();

    // ---- layer 1: h1 = relu(gcn(x, W1, b1)) -----------------------------
    run_gemm(x, -1, W1, nullptr, nullptr, 0, NN, DIN, DH, 0);   // g_h = x@W1
    run_agg128(b1, nullptr, 2, 1);                              // -> g_h1

    // ---- layer 2: h2 = relu(gcn(h1, W2, b2)) ----------------------------
    run_gemm(nullptr, 2, W2, nullptr, nullptr, 0, NN, DH, DH, 0);
    run_agg128(b2, nullptr, 2, 1);

    // ---- layer 3: z = gcn(h2, W3, b3) -----------------------------------
    run_gemm(nullptr, 2, W3, nullptr, nullptr, 0, NN, DH, DE, 0);
    run_agg64(b3, z, -1, 0);

    // ---- decoder: x_hat = relu(z@Wd1+bd1)@Wd2 + bd2 ---------------------
    run_gemm(z, -1, Wd1, bd1, nullptr, 2, NN, DE, DH, 1);
    run_gemm(nullptr, 2, Wd2, bd2, xhat, -1, NN, DH, DIN, 0);
}